// round 16
// baseline (speedup 1.0000x reference)
#include <cuda_runtime.h>
#include <cuda_fp16.h>
#include <cstdint>
#include <math.h>

#define BB 4
#define TT 2048
#define CC 1024
#define MT (BB*TT)            /* 8192 flattened token rows */

typedef __half hf;

// ---------------- scratch (__device__ globals; no allocs allowed) ----------
__device__ hf    g_xh[MT*CC];
__device__ hf    g_wq[CC*CC],  g_wk[CC*CC],  g_wv[CC*CC];
__device__ hf    g_qh[MT*CC];
__device__ hf    g_kh[MT*CC];
__device__ hf    g_v[MT*CC];
__device__ hf    g_e[(size_t)BB*TT*TT];     /* unnormalized exp(score) */
__device__ float g_rs[MT];                  /* per-row 1/sum(e) */

// ---------------- helpers ---------------------------------------------------
__device__ __forceinline__ uint32_t smem_u32(const void* p) {
    uint32_t a;
    asm("{ .reg .u64 t; cvta.to.shared.u64 t, %1; cvt.u32.u64 %0, t; }"
        : "=r"(a) : "l"(p));
    return a;
}
__device__ __forceinline__ void cpa16(uint32_t d, const void* s) {
    asm volatile("cp.async.cg.shared.global [%0], [%1], 16;" :: "r"(d), "l"(s));
}
__device__ __forceinline__ void cp_commit() {
    asm volatile("cp.async.commit_group;");
}
__device__ __forceinline__ void ldsm4(uint32_t* r, uint32_t addr) {
    asm volatile("ldmatrix.sync.aligned.m8n8.x4.shared.b16 {%0,%1,%2,%3}, [%4];"
        : "=r"(r[0]), "=r"(r[1]), "=r"(r[2]), "=r"(r[3]) : "r"(addr));
}
__device__ __forceinline__ void ldsm4t(uint32_t* r, uint32_t addr) {
    asm volatile("ldmatrix.sync.aligned.m8n8.x4.trans.shared.b16 {%0,%1,%2,%3}, [%4];"
        : "=r"(r[0]), "=r"(r[1]), "=r"(r[2]), "=r"(r[3]) : "r"(addr));
}
__device__ __forceinline__ void mma16816(float* c, const uint32_t* a,
                                         uint32_t b0, uint32_t b1) {
    asm volatile("mma.sync.aligned.m16n8k16.row.col.f32.f16.f16.f32 "
        "{%0,%1,%2,%3}, {%4,%5,%6,%7}, {%8,%9}, {%0,%1,%2,%3};"
        : "+f"(c[0]), "+f"(c[1]), "+f"(c[2]), "+f"(c[3])
        : "r"(a[0]), "r"(a[1]), "r"(a[2]), "r"(a[3]), "r"(b0), "r"(b1));
}

// ---------------------------------------------------------------------------
// fp16 warp-MMA GEMM core (NT): acc += A . B^T, A:[M,K], B:[N,K] row-major.
// CTA tile 128x256, BK=64, 8 warps (2m x 4n, warp tile 64x64, acc 128 regs).
// 3-stage cp.async pipeline, ONE barrier per chunk. Pitch-72 smem rows.
// ---------------------------------------------------------------------------
#define BM 128
#define BN 256
#define SP 72                      /* smem row pitch, elements */
#define SA  (BM * SP * 2)          /* 18432 B: A tile 128x64 */
#define SBB (BN * SP * 2)          /* 36864 B: B tile 256x64 */
#define STG (SA + SBB)             /* 55296 B per stage */
#define GSM (3 * STG)              /* 165888 B */

__device__ __forceinline__ void gemm_core(
    const hf* __restrict__ Ah, const hf* __restrict__ Bh,
    int K, int rm, int cn, int kmax, char* smem, float acc[4][8][4])
{
    uint32_t sb = smem_u32(smem);

    int tid = threadIdx.x, lane = tid & 31, wid = tid >> 5;
    int wm = wid & 1, wn = wid >> 1;

    int l_row = tid >> 3;          // 0..31
    int l_c   = (tid & 7) * 8;     // element col 0..56 (16B chunks)

    uint32_t aoff = ((uint32_t)(wm * 64 + (lane & 15)) * SP + (lane >> 4) * 8) * 2u;
    uint32_t boff = ((uint32_t)(wn * 64 + ((lane >> 4) & 1) * 8 + (lane & 7)) * SP
                     + ((lane >> 3) & 1) * 8) * 2u;

    int nch = kmax >> 6;

#define LOADC(cc) do {                                                        \
    uint32_t _b = sb + (uint32_t)((cc) % 3) * STG;                            \
    size_t _k0 = (size_t)(cc) * 64;                                           \
    _Pragma("unroll")                                                         \
    for (int _i = 0; _i < 4; _i++) {                                          \
        int _r = l_row + 32 * _i;                                             \
        cpa16(_b + ((uint32_t)_r * SP + l_c) * 2u,                            \
              Ah + (size_t)(rm + _r) * K + _k0 + l_c);                        \
    }                                                                         \
    _Pragma("unroll")                                                         \
    for (int _i = 0; _i < 8; _i++) {                                          \
        int _r = l_row + 32 * _i;                                             \
        cpa16(_b + SA + ((uint32_t)_r * SP + l_c) * 2u,                       \
              Bh + (size_t)(cn + _r) * K + _k0 + l_c);                        \
    }                                                                         \
    cp_commit();                                                              \
} while (0)

    LOADC(0);
    if (nch > 1) LOADC(1);

    for (int c = 0; c < nch; c++) {
        if (c + 1 < nch) asm volatile("cp.async.wait_group 1;");
        else             asm volatile("cp.async.wait_group 0;");
        __syncthreads();
        if (c + 2 < nch) LOADC(c + 2);   // stage (c+2)%3 last read in chunk c-1

        uint32_t sbase = sb + (uint32_t)(c % 3) * STG;
        #pragma unroll
        for (int kk = 0; kk < 4; kk++) {
            uint32_t a[4][4];
            #pragma unroll
            for (int mi = 0; mi < 4; mi++)
                ldsm4(a[mi], sbase + aoff + mi * (16 * SP * 2) + kk * 32);
            #pragma unroll
            for (int np = 0; np < 4; np++) {
                uint32_t b[4];
                ldsm4(b, sbase + SA + boff + np * (16 * SP * 2) + kk * 32);
                #pragma unroll
                for (int mi = 0; mi < 4; mi++) {
                    mma16816(acc[mi][2 * np],     a[mi], b[0], b[1]);
                    mma16816(acc[mi][2 * np + 1], a[mi], b[2], b[3]);
                }
            }
        }
    }
#undef LOADC
    __syncthreads();
}

#define EPI_IDX()                                                             \
    int lane = threadIdx.x & 31, wid = threadIdx.x >> 5;                      \
    int wm = wid & 1, wn = wid >> 1;                                          \
    int g4 = lane >> 2, tg = lane & 3;

#define ZERO_ACC(acc)                                                         \
    _Pragma("unroll")                                                         \
    for (int _a = 0; _a < 4; _a++)                                            \
        _Pragma("unroll")                                                     \
        for (int _b = 0; _b < 8; _b++)                                        \
            _Pragma("unroll")                                                 \
            for (int _c = 0; _c < 4; _c++) (acc)[_a][_b][_c] = 0.f;

// ---------------------------------------------------------------------------
// Fused QKV projection (single-pass fp16): z selects weight and destination.
// ---------------------------------------------------------------------------
__global__ __launch_bounds__(256, 1)
void proj_kernel(const hf* __restrict__ xh,
                 const hf* __restrict__ wq, const hf* __restrict__ wk,
                 const hf* __restrict__ wv,
                 hf* __restrict__ qh, hf* __restrict__ kh, hf* __restrict__ v)
{
    extern __shared__ char smem[];
    int rm = blockIdx.y * BM, cn = blockIdx.x * BN, z = blockIdx.z;
    const hf* B  = (z == 0) ? wq : (z == 1) ? wk : wv;
    hf* dst      = (z == 0) ? qh : (z == 1) ? kh : v;

    float acc[4][8][4];
    ZERO_ACC(acc);
    gemm_core(xh, B, CC, rm, cn, CC, smem, acc);

    EPI_IDX();
    #pragma unroll
    for (int mi = 0; mi < 4; mi++)
        #pragma unroll
        for (int ni = 0; ni < 8; ni++) {
            int r0 = rm + wm * 64 + mi * 16 + g4;
            int cb = cn + wn * 64 + ni * 8 + tg * 2;
            *(__half2*)(dst + (size_t)r0 * CC + cb) =
                __halves2half2(__float2half_rn(acc[mi][ni][0]),
                               __float2half_rn(acc[mi][ni][1]));
            *(__half2*)(dst + (size_t)(r0 + 8) * CC + cb) =
                __halves2half2(__float2half_rn(acc[mi][ni][2]),
                               __float2half_rn(acc[mi][ni][3]));
        }
}

// ---------------------------------------------------------------------------
// e = exp(scale * q @ k^T - 4)  — causal tile early-exit, fp16 output,
// masked to 0 above the diagonal. Normalization deferred to PV epilogue.
// ---------------------------------------------------------------------------
__global__ __launch_bounds__(256, 1)
void score_kernel(const hf* __restrict__ qh, const hf* __restrict__ kh,
                  hf* __restrict__ e, float scale)
{
    extern __shared__ char smem[];
    int rm = blockIdx.y * BM, cn = blockIdx.x * BN;
    if (cn > rm + BM - 1) return;                 // fully-masked tile

    int bz = blockIdx.z;
    qh += (size_t)bz * TT * CC;  kh += (size_t)bz * TT * CC;
    e  += (size_t)bz * TT * TT;

    float acc[4][8][4];
    ZERO_ACC(acc);
    gemm_core(qh, kh, CC, rm, cn, CC, smem, acc);

    EPI_IDX();
    #pragma unroll
    for (int mi = 0; mi < 4; mi++)
        #pragma unroll
        for (int ni = 0; ni < 8; ni++) {
            int r0 = rm + wm * 64 + mi * 16 + g4;
            int cb = cn + wn * 64 + ni * 8 + tg * 2;
            float e0 = (cb     <= r0) ? __expf(acc[mi][ni][0] * scale - 4.f) : 0.f;
            float e1 = (cb + 1 <= r0) ? __expf(acc[mi][ni][1] * scale - 4.f) : 0.f;
            int r1 = r0 + 8;
            float e2 = (cb     <= r1) ? __expf(acc[mi][ni][2] * scale - 4.f) : 0.f;
            float e3 = (cb + 1 <= r1) ? __expf(acc[mi][ni][3] * scale - 4.f) : 0.f;
            *(__half2*)(e + (size_t)r0 * TT + cb) =
                __halves2half2(__float2half_rn(e0), __float2half_rn(e1));
            *(__half2*)(e + (size_t)r1 * TT + cb) =
                __halves2half2(__float2half_rn(e2), __float2half_rn(e3));
        }
}

// ---------------------------------------------------------------------------
// per-row inverse sums: rs[row] = 1 / sum_{k<=t} e[row][k]
// ---------------------------------------------------------------------------
__global__ __launch_bounds__(256)
void rowsum_inv(const hf* __restrict__ e, float* __restrict__ rs)
{
    int row = blockIdx.x;                 // 0..MT-1
    int b = row >> 11, t = row & 2047;
    const hf* p = e + ((size_t)b * TT + t) * TT;
    int n = t + 1;
    int tid = threadIdx.x;

    __shared__ float red[8];
    int lane = tid & 31, wrp = tid >> 5;

    float sum = 0.f;
    for (int i = tid; i < n; i += 256) sum += __half2float(p[i]);
    #pragma unroll
    for (int s = 16; s > 0; s >>= 1)
        sum += __shfl_xor_sync(0xffffffffu, sum, s);
    if (lane == 0) red[wrp] = sum;
    __syncthreads();
    if (tid == 0) {
        float tot = red[0];
        #pragma unroll
        for (int j = 1; j < 8; j++) tot += red[j];
        rs[row] = 1.f / tot;
    }
}

// ---------------------------------------------------------------------------
// out = (E @ V) * inv_sum  (NN): V consumed directly via ldmatrix.trans.
// CTA tile 128x256, warp tile 64x64. B tile 64 k-rows x 256 n-cols,
// pitch 264. 3-stage pipeline, k-loop truncated at the diagonal.
// ---------------------------------------------------------------------------
#define BP 264                       /* pv B tile pitch, elements */
#define SBV (64 * BP * 2)            /* 33792 B */
#define STV (SA + SBV)               /* 52224 B per stage */
#define PVSM (3 * STV)               /* 156672 B */

__global__ __launch_bounds__(256, 1)
void pv_kernel(const hf* __restrict__ e, const hf* __restrict__ v,
               const float* __restrict__ rs, float* __restrict__ out)
{
    extern __shared__ char smem[];
    int iy = gridDim.y - 1 - blockIdx.y;          // heavy tiles first
    int rm = iy * BM, cn = blockIdx.x * BN;
    int kmax = rm + BM;

    int bz = blockIdx.z;
    e   += (size_t)bz * TT * TT;
    v   += (size_t)bz * TT * CC;  out += (size_t)bz * TT * CC;
    rs  += (size_t)bz * TT;

    uint32_t sb = smem_u32(smem);

    int tid = threadIdx.x, lane = tid & 31, wid = tid >> 5;
    int wm = wid & 1, wn = wid >> 1;

    int la_row = tid >> 3;            // A loader: 0..31 (x4 iters)
    int la_c   = (tid & 7) * 8;
    int lb_row = tid >> 5;            // B loader: one row per warp (x8 iters)
    int lb_c   = (tid & 31) * 8;      // 0..248

    uint32_t aoff  = ((uint32_t)(wm * 64 + (lane & 15)) * SP + (lane >> 4) * 8) * 2u;
    uint32_t bofft = ((uint32_t)((lane & 7) + ((lane >> 3) & 1) * 8) * BP
                      + (uint32_t)(wn * 64 + ((lane >> 4) & 1) * 8)) * 2u;

    float acc[4][8][4];
    ZERO_ACC(acc);

    int nch = kmax >> 6;

#define LOADPV(cc) do {                                                       \
    uint32_t _b = sb + (uint32_t)((cc) % 3) * STV;                            \
    size_t _k0 = (size_t)(cc) * 64;                                           \
    _Pragma("unroll")                                                         \
    for (int _i = 0; _i < 4; _i++) {                                          \
        int _r = la_row + 32 * _i;                                            \
        cpa16(_b + ((uint32_t)_r * SP + la_c) * 2u,                           \
              e + (size_t)(rm + _r) * TT + _k0 + la_c);                       \
    }                                                                         \
    _Pragma("unroll")                                                         \
    for (int _i = 0; _i < 8; _i++) {                                          \
        int _r = lb_row + 8 * _i;                                             \
        cpa16(_b + SA + ((uint32_t)_r * BP + lb_c) * 2u,                      \
              v + (size_t)(_k0 + _r) * CC + cn + lb_c);                       \
    }                                                                         \
    cp_commit();                                                              \
} while (0)

    LOADPV(0);
    if (nch > 1) LOADPV(1);

    for (int c = 0; c < nch; c++) {
        if (c + 1 < nch) asm volatile("cp.async.wait_group 1;");
        else             asm volatile("cp.async.wait_group 0;");
        __syncthreads();
        if (c + 2 < nch) LOADPV(c + 2);

        uint32_t sbase = sb + (uint32_t)(c % 3) * STV;
        #pragma unroll
        for (int kk = 0; kk < 4; kk++) {
            uint32_t a[4][4];
            #pragma unroll
            for (int mi = 0; mi < 4; mi++)
                ldsm4(a[mi], sbase + aoff + mi * (16 * SP * 2) + kk * 32);
            #pragma unroll
            for (int np = 0; np < 4; np++) {
                uint32_t b[4];
                ldsm4t(b, sbase + SA + bofft
                          + ((uint32_t)kk * 16 * BP + np * 16) * 2u);
                #pragma unroll
                for (int mi = 0; mi < 4; mi++) {
                    mma16816(acc[mi][2 * np],     a[mi], b[0], b[1]);
                    mma16816(acc[mi][2 * np + 1], a[mi], b[2], b[3]);
                }
            }
        }
    }
#undef LOADPV

    int g4 = lane >> 2, tg = lane & 3;
    #pragma unroll
    for (int mi = 0; mi < 4; mi++) {
        int r0 = rm + wm * 64 + mi * 16 + g4;
        float s0 = rs[r0], s1 = rs[r0 + 8];
        #pragma unroll
        for (int ni = 0; ni < 8; ni++) {
            int cb = cn + wn * 64 + ni * 8 + tg * 2;
            *(float2*)(out + (size_t)r0 * CC + cb) =
                make_float2(acc[mi][ni][0] * s0, acc[mi][ni][1] * s0);
            *(float2*)(out + (size_t)(r0 + 8) * CC + cb) =
                make_float2(acc[mi][ni][2] * s1, acc[mi][ni][3] * s1);
        }
    }
}

// ---------------------------------------------------------------------------
// input conversions (fp32 -> fp16, rounded)
// ---------------------------------------------------------------------------
__global__ __launch_bounds__(256)
void conv_h(const float* __restrict__ in, hf* __restrict__ h, int n)
{
    int i = blockIdx.x * 256 + threadIdx.x;
    if (i < n) h[i] = __float2half_rn(in[i]);
}
__global__ __launch_bounds__(256)
void conv3(const float* __restrict__ a, const float* __restrict__ b,
           const float* __restrict__ c, hf* __restrict__ oa,
           hf* __restrict__ ob, hf* __restrict__ oc, int n)
{
    int z = blockIdx.y;
    const float* in = (z == 0) ? a : (z == 1) ? b : c;
    hf* o = (z == 0) ? oa : (z == 1) ? ob : oc;
    int i = blockIdx.x * 256 + threadIdx.x;
    if (i < n) o[i] = __float2half_rn(in[i]);
}

// ---------------------------------------------------------------------------
extern "C" void kernel_launch(void* const* d_in, const int* in_sizes, int n_in,
                              void* d_out, int out_size)
{
    const float* x  = (const float*)d_in[0];
    const float* Wk = (const float*)d_in[1];
    const float* Wq = (const float*)d_in[2];
    const float* Wv = (const float*)d_in[3];
    float* out = (float*)d_out;

    hf *xh, *wq, *wk, *wv, *qh, *kh, *v, *e;
    float *rs;
    cudaGetSymbolAddress((void**)&xh, g_xh);
    cudaGetSymbolAddress((void**)&wq, g_wq); cudaGetSymbolAddress((void**)&wk, g_wk);
    cudaGetSymbolAddress((void**)&wv, g_wv);
    cudaGetSymbolAddress((void**)&qh, g_qh); cudaGetSymbolAddress((void**)&kh, g_kh);
    cudaGetSymbolAddress((void**)&v, g_v);
    cudaGetSymbolAddress((void**)&e, g_e);
    cudaGetSymbolAddress((void**)&rs, g_rs);

    cudaFuncSetAttribute(proj_kernel,  cudaFuncAttributeMaxDynamicSharedMemorySize, GSM);
    cudaFuncSetAttribute(score_kernel, cudaFuncAttributeMaxDynamicSharedMemorySize, GSM);
    cudaFuncSetAttribute(pv_kernel,    cudaFuncAttributeMaxDynamicSharedMemorySize, PVSM);

    const float scale = 1.0f / 32.0f;   // C^-0.5

    // 1) input conversions (all fp16 hi)
    conv_h<<<(MT * CC + 255) / 256, 256>>>(x, xh, MT * CC);
    conv3<<<dim3((CC * CC + 255) / 256, 3), 256>>>(Wq, Wk, Wv, wq, wk, wv, CC * CC);

    // 2) fused QKV projection, single-pass fp16 (CTA tile 128x256)
    proj_kernel<<<dim3(CC / BN, MT / BM, 3), 256, GSM>>>(
        xh, wq, wk, wv, qh, kh, v);

    // 3) e = exp(scale*q@k^T - 4), masked, fp16 (causal early-exit grid)
    score_kernel<<<dim3(TT / BN, TT / BM, BB), 256, GSM>>>(qh, kh, e, scale);

    // 4) per-row inverse sums
    rowsum_inv<<<MT, 256>>>(e, rs);

    // 5) out = (E @ V) * inv_sum
    pv_kernel<<<dim3(CC / BN, TT / BM, BB), 256, PVSM>>>(e, v, rs, out);
}

// round 17
// speedup vs baseline: 1.1329x; 1.1329x over previous
#include <cuda_runtime.h>
#include <cuda_fp16.h>
#include <cstdint>
#include <math.h>

#define BB 4
#define TT 2048
#define CC 1024
#define MT (BB*TT)            /* 8192 flattened token rows */

typedef __half hf;

// ---------------- scratch (__device__ globals; no allocs allowed) ----------
__device__ hf    g_xh[MT*CC];
__device__ hf    g_wq[CC*CC],  g_wk[CC*CC],  g_wv[CC*CC];
__device__ hf    g_qh[MT*CC];
__device__ hf    g_kh[MT*CC];
__device__ hf    g_v[MT*CC];
__device__ hf    g_e[(size_t)BB*TT*TT];     /* unnormalized exp(score) */
__device__ float g_rs[MT];                  /* per-row sum(e), atomically built */

// ---------------- helpers ---------------------------------------------------
__device__ __forceinline__ uint32_t smem_u32(const void* p) {
    uint32_t a;
    asm("{ .reg .u64 t; cvta.to.shared.u64 t, %1; cvt.u32.u64 %0, t; }"
        : "=r"(a) : "l"(p));
    return a;
}
__device__ __forceinline__ void cpa16(uint32_t d, const void* s) {
    asm volatile("cp.async.cg.shared.global [%0], [%1], 16;" :: "r"(d), "l"(s));
}
__device__ __forceinline__ void cp_commit() {
    asm volatile("cp.async.commit_group;");
}
__device__ __forceinline__ void ldsm4(uint32_t* r, uint32_t addr) {
    asm volatile("ldmatrix.sync.aligned.m8n8.x4.shared.b16 {%0,%1,%2,%3}, [%4];"
        : "=r"(r[0]), "=r"(r[1]), "=r"(r[2]), "=r"(r[3]) : "r"(addr));
}
__device__ __forceinline__ void ldsm4t(uint32_t* r, uint32_t addr) {
    asm volatile("ldmatrix.sync.aligned.m8n8.x4.trans.shared.b16 {%0,%1,%2,%3}, [%4];"
        : "=r"(r[0]), "=r"(r[1]), "=r"(r[2]), "=r"(r[3]) : "r"(addr));
}
__device__ __forceinline__ void mma16816(float* c, const uint32_t* a,
                                         uint32_t b0, uint32_t b1) {
    asm volatile("mma.sync.aligned.m16n8k16.row.col.f32.f16.f16.f32 "
        "{%0,%1,%2,%3}, {%4,%5,%6,%7}, {%8,%9}, {%0,%1,%2,%3};"
        : "+f"(c[0]), "+f"(c[1]), "+f"(c[2]), "+f"(c[3])
        : "r"(a[0]), "r"(a[1]), "r"(a[2]), "r"(a[3]), "r"(b0), "r"(b1));
}

// ---------------------------------------------------------------------------
// fp16 warp-MMA GEMM core (NT): acc += A . B^T, A:[M,K], B:[N,K] row-major.
// CTA tile 128x128, BK=64, 8 warps (4m x 2n, warp tile 32x64),
// 2-stage cp.async. Pitch-72 smem rows (conflict-free ldmatrix).
// ---------------------------------------------------------------------------
#define SP 72                      /* smem row pitch, elements */
#define TB (128 * SP * 2)          /* 18432 B per 128x64 tile buffer */
#define PSM (4 * TB)               /* {A,B} x 2 stages = 73728 B */

__device__ __forceinline__ void gemm_core(
    const hf* __restrict__ Ah, const hf* __restrict__ Bh,
    int K, int rm, int cn, int kmax, char* smem, float acc[2][8][4])
{
    uint32_t sb = smem_u32(smem);
    uint32_t aH[2] = { sb,          sb + TB };
    uint32_t bS[2] = { sb + 2*TB,   sb + 3*TB };

    int tid = threadIdx.x, lane = tid & 31, wid = tid >> 5;
    int wm = wid & 3, wn = wid >> 2;

    int l_row = tid >> 3;          // 0..31
    int l_c   = (tid & 7) * 8;     // element col 0..56 (16B chunks)

    uint32_t aoff = ((uint32_t)(wm * 32 + (lane & 15)) * SP + (lane >> 4) * 8) * 2u;
    uint32_t boff = ((uint32_t)(wn * 64 + ((lane >> 4) & 1) * 8 + (lane & 7)) * SP
                     + ((lane >> 3) & 1) * 8) * 2u;

    int nch = kmax >> 6;

#define LOADC(cc) do {                                                        \
    int _s = (cc) & 1; size_t _k0 = (size_t)(cc) * 64;                        \
    _Pragma("unroll")                                                         \
    for (int _i = 0; _i < 4; _i++) {                                          \
        int _r = l_row + 32 * _i;                                             \
        uint32_t _so = ((uint32_t)_r * SP + l_c) * 2u;                        \
        cpa16(aH[_s] + _so, Ah + (size_t)(rm + _r) * K + _k0 + l_c);          \
        cpa16(bS[_s] + _so, Bh + (size_t)(cn + _r) * K + _k0 + l_c);          \
    }                                                                         \
    cp_commit();                                                              \
} while (0)

    LOADC(0);

    for (int c = 0; c < nch; c++) {
        if (c + 1 < nch) {
            LOADC(c + 1);
            asm volatile("cp.async.wait_group 1;");
        } else {
            asm volatile("cp.async.wait_group 0;");
        }
        __syncthreads();

        int s = c & 1;
        #pragma unroll
        for (int kk = 0; kk < 4; kk++) {
            uint32_t ah[2][4];
            #pragma unroll
            for (int mi = 0; mi < 2; mi++)
                ldsm4(ah[mi], aH[s] + aoff + mi * (16 * SP * 2) + kk * 32);
            #pragma unroll
            for (int np = 0; np < 4; np++) {
                uint32_t b[4];
                ldsm4(b, bS[s] + boff + np * (16 * SP * 2) + kk * 32);
                #pragma unroll
                for (int mi = 0; mi < 2; mi++) {
                    mma16816(acc[mi][2 * np],     ah[mi], b[0], b[1]);
                    mma16816(acc[mi][2 * np + 1], ah[mi], b[2], b[3]);
                }
            }
        }
        __syncthreads();
    }
#undef LOADC
}

#define EPI_IDX()                                                             \
    int lane = threadIdx.x & 31, wid = threadIdx.x >> 5;                      \
    int wm = wid & 3, wn = wid >> 2;                                          \
    int g4 = lane >> 2, tg = lane & 3;

#define ZERO_ACC(acc)                                                         \
    _Pragma("unroll")                                                         \
    for (int _a = 0; _a < 2; _a++)                                            \
        _Pragma("unroll")                                                     \
        for (int _b = 0; _b < 8; _b++)                                        \
            _Pragma("unroll")                                                 \
            for (int _c = 0; _c < 4; _c++) (acc)[_a][_b][_c] = 0.f;

// ---------------------------------------------------------------------------
// Fused QKV projection (single-pass fp16): z selects weight and destination.
// ---------------------------------------------------------------------------
__global__ __launch_bounds__(256, 2)
void proj_kernel(const hf* __restrict__ xh,
                 const hf* __restrict__ wq, const hf* __restrict__ wk,
                 const hf* __restrict__ wv,
                 hf* __restrict__ qh, hf* __restrict__ kh, hf* __restrict__ v)
{
    extern __shared__ char smem[];
    int rm = blockIdx.y * 128, cn = blockIdx.x * 128, z = blockIdx.z;
    const hf* B  = (z == 0) ? wq : (z == 1) ? wk : wv;
    hf* dst      = (z == 0) ? qh : (z == 1) ? kh : v;

    float acc[2][8][4];
    ZERO_ACC(acc);
    gemm_core(xh, B, CC, rm, cn, CC, smem, acc);

    EPI_IDX();
    #pragma unroll
    for (int mi = 0; mi < 2; mi++)
        #pragma unroll
        for (int ni = 0; ni < 8; ni++) {
            int r0 = rm + wm * 32 + mi * 16 + g4;
            int cb = cn + wn * 64 + ni * 8 + tg * 2;
            *(__half2*)(dst + (size_t)r0 * CC + cb) =
                __halves2half2(__float2half_rn(acc[mi][ni][0]),
                               __float2half_rn(acc[mi][ni][1]));
            *(__half2*)(dst + (size_t)(r0 + 8) * CC + cb) =
                __halves2half2(__float2half_rn(acc[mi][ni][2]),
                               __float2half_rn(acc[mi][ni][3]));
        }
}

// ---------------------------------------------------------------------------
// e = exp(scale * q @ k^T - 4)  — triangular tile launch, fp16 output,
// masked to 0 above the diagonal. Row sums accumulated into rs[] via
// warp-reduced atomicAdd (normalization deferred to PV epilogue).
// ---------------------------------------------------------------------------
__global__ __launch_bounds__(256, 2)
void score_kernel(const hf* __restrict__ qh, const hf* __restrict__ kh,
                  hf* __restrict__ e, float* __restrict__ rs, float scale)
{
    extern __shared__ char smem[];
    int ti = blockIdx.x;                          // 0..135
    int i = (int)((sqrtf(8.f * ti + 1.f) - 1.f) * 0.5f);
    while ((i + 1) * (i + 2) / 2 <= ti) i++;
    while (i * (i + 1) / 2 > ti) i--;
    int j = ti - i * (i + 1) / 2;
    int rm = i * 128, cn = j * 128;

    int bz = blockIdx.z;
    qh += (size_t)bz * TT * CC;  kh += (size_t)bz * TT * CC;
    e  += (size_t)bz * TT * TT;  rs += (size_t)bz * TT;

    float acc[2][8][4];
    ZERO_ACC(acc);
    gemm_core(qh, kh, CC, rm, cn, CC, smem, acc);

    EPI_IDX();
    #pragma unroll
    for (int mi = 0; mi < 2; mi++) {
        int r0 = rm + wm * 32 + mi * 16 + g4;
        int r1 = r0 + 8;
        float sum0 = 0.f, sum1 = 0.f;
        #pragma unroll
        for (int ni = 0; ni < 8; ni++) {
            int cb = cn + wn * 64 + ni * 8 + tg * 2;
            float e0 = (cb     <= r0) ? __expf(acc[mi][ni][0] * scale - 4.f) : 0.f;
            float e1 = (cb + 1 <= r0) ? __expf(acc[mi][ni][1] * scale - 4.f) : 0.f;
            float e2 = (cb     <= r1) ? __expf(acc[mi][ni][2] * scale - 4.f) : 0.f;
            float e3 = (cb + 1 <= r1) ? __expf(acc[mi][ni][3] * scale - 4.f) : 0.f;
            sum0 += e0 + e1;
            sum1 += e2 + e3;
            *(__half2*)(e + (size_t)r0 * TT + cb) =
                __halves2half2(__float2half_rn(e0), __float2half_rn(e1));
            *(__half2*)(e + (size_t)r1 * TT + cb) =
                __halves2half2(__float2half_rn(e2), __float2half_rn(e3));
        }
        // reduce across the 4 tg lanes (same row), then one atomic per row
        sum0 += __shfl_xor_sync(0xffffffffu, sum0, 1);
        sum0 += __shfl_xor_sync(0xffffffffu, sum0, 2);
        sum1 += __shfl_xor_sync(0xffffffffu, sum1, 1);
        sum1 += __shfl_xor_sync(0xffffffffu, sum1, 2);
        if (tg == 0) {
            atomicAdd(rs + r0, sum0);
            atomicAdd(rs + r1, sum1);
        }
    }
}

// ---------------------------------------------------------------------------
// out = (E @ V) / rowsum  (NN): V consumed directly via ldmatrix.trans.
// k-loop truncated at the diagonal. B tile 64x128, pitch 136. 2-stage.
// ---------------------------------------------------------------------------
#define BP 136                       /* pv B tile pitch, elements */
#define PVA TB                       /* A buffer: 128 x 64, pitch 72 */
#define PVB (64 * BP * 2)            /* 17408 B */
#define PVSM (2 * (PVA + PVB))       /* 71680 B */

__global__ __launch_bounds__(256, 2)
void pv_kernel(const hf* __restrict__ e, const hf* __restrict__ v,
               const float* __restrict__ rs, float* __restrict__ out)
{
    extern __shared__ char smem[];
    int iy = gridDim.y - 1 - blockIdx.y;          // heavy tiles first
    int rm = iy * 128, cn = blockIdx.x * 128;
    int kmax = rm + 128;

    int bz = blockIdx.z;
    e   += (size_t)bz * TT * TT;
    v   += (size_t)bz * TT * CC;  out += (size_t)bz * TT * CC;
    rs  += (size_t)bz * TT;

    uint32_t sb = smem_u32(smem);
    uint32_t aH[2] = { sb,               sb + (PVA + PVB) };
    uint32_t bS[2] = { sb + PVA,         sb + (PVA + PVB) + PVA };

    int tid = threadIdx.x, lane = tid & 31, wid = tid >> 5;
    int wm = wid & 3, wn = wid >> 2;

    int la_row = tid >> 3;            // A loader: 0..31
    int la_c   = (tid & 7) * 8;
    int lb_row = tid >> 4;            // B loader: 0..15 (x4 iters)
    int lb_c   = (tid & 15) * 8;      // 0..120

    uint32_t aoff  = ((uint32_t)(wm * 32 + (lane & 15)) * SP + (lane >> 4) * 8) * 2u;
    uint32_t bofft = ((uint32_t)((lane & 7) + ((lane >> 3) & 1) * 8) * BP
                      + (uint32_t)(wn * 64 + ((lane >> 4) & 1) * 8)) * 2u;

    float acc[2][8][4];
    ZERO_ACC(acc);

    int nch = kmax >> 6;

#define LOADPV(cc) do {                                                       \
    int _s = (cc) & 1; size_t _k0 = (size_t)(cc) * 64;                        \
    _Pragma("unroll")                                                         \
    for (int _i = 0; _i < 4; _i++) {                                          \
        int _r = la_row + 32 * _i;                                            \
        cpa16(aH[_s] + ((uint32_t)_r * SP + la_c) * 2u,                       \
              e + (size_t)(rm + _r) * TT + _k0 + la_c);                       \
    }                                                                         \
    _Pragma("unroll")                                                         \
    for (int _i = 0; _i < 4; _i++) {                                          \
        int _r = lb_row + 16 * _i;                                            \
        cpa16(bS[_s] + ((uint32_t)_r * BP + lb_c) * 2u,                       \
              v + (size_t)(_k0 + _r) * CC + cn + lb_c);                       \
    }                                                                         \
    cp_commit();                                                              \
} while (0)

    LOADPV(0);

    for (int c = 0; c < nch; c++) {
        if (c + 1 < nch) {
            LOADPV(c + 1);
            asm volatile("cp.async.wait_group 1;");
        } else {
            asm volatile("cp.async.wait_group 0;");
        }
        __syncthreads();

        int s = c & 1;
        #pragma unroll
        for (int kk = 0; kk < 4; kk++) {
            uint32_t ah[2][4];
            #pragma unroll
            for (int mi = 0; mi < 2; mi++)
                ldsm4(ah[mi], aH[s] + aoff + mi * (16 * SP * 2) + kk * 32);
            #pragma unroll
            for (int np = 0; np < 4; np++) {
                uint32_t b[4];
                ldsm4t(b, bS[s] + bofft + ((uint32_t)kk * 16 * BP + np * 16) * 2u);
                #pragma unroll
                for (int mi = 0; mi < 2; mi++) {
                    mma16816(acc[mi][2 * np],     ah[mi], b[0], b[1]);
                    mma16816(acc[mi][2 * np + 1], ah[mi], b[2], b[3]);
                }
            }
        }
        __syncthreads();
    }
#undef LOADPV

    int g4 = lane >> 2, tg = lane & 3;
    #pragma unroll
    for (int mi = 0; mi < 2; mi++) {
        int r0 = rm + wm * 32 + mi * 16 + g4;
        float s0 = 1.f / rs[r0], s1 = 1.f / rs[r0 + 8];
        #pragma unroll
        for (int ni = 0; ni < 8; ni++) {
            int cb = cn + wn * 64 + ni * 8 + tg * 2;
            *(float2*)(out + (size_t)r0 * CC + cb) =
                make_float2(acc[mi][ni][0] * s0, acc[mi][ni][1] * s0);
            *(float2*)(out + (size_t)(r0 + 8) * CC + cb) =
                make_float2(acc[mi][ni][2] * s1, acc[mi][ni][3] * s1);
        }
    }
}

// ---------------------------------------------------------------------------
// input conversions (fp32 -> fp16); conv_h also zeroes the rowsum buffer
// ---------------------------------------------------------------------------
__global__ __launch_bounds__(256)
void conv_h(const float* __restrict__ in, hf* __restrict__ h,
            float* __restrict__ rs, int n)
{
    int i = blockIdx.x * 256 + threadIdx.x;
    if (i < n) h[i] = __float2half_rn(in[i]);
    if (i < MT) rs[i] = 0.f;
}
__global__ __launch_bounds__(256)
void conv3(const float* __restrict__ a, const float* __restrict__ b,
           const float* __restrict__ c, hf* __restrict__ oa,
           hf* __restrict__ ob, hf* __restrict__ oc, int n)
{
    int z = blockIdx.y;
    const float* in = (z == 0) ? a : (z == 1) ? b : c;
    hf* o = (z == 0) ? oa : (z == 1) ? ob : oc;
    int i = blockIdx.x * 256 + threadIdx.x;
    if (i < n) o[i] = __float2half_rn(in[i]);
}

// ---------------------------------------------------------------------------
extern "C" void kernel_launch(void* const* d_in, const int* in_sizes, int n_in,
                              void* d_out, int out_size)
{
    const float* x  = (const float*)d_in[0];
    const float* Wk = (const float*)d_in[1];
    const float* Wq = (const float*)d_in[2];
    const float* Wv = (const float*)d_in[3];
    float* out = (float*)d_out;

    hf *xh, *wq, *wk, *wv, *qh, *kh, *v, *e;
    float *rs;
    cudaGetSymbolAddress((void**)&xh, g_xh);
    cudaGetSymbolAddress((void**)&wq, g_wq); cudaGetSymbolAddress((void**)&wk, g_wk);
    cudaGetSymbolAddress((void**)&wv, g_wv);
    cudaGetSymbolAddress((void**)&qh, g_qh); cudaGetSymbolAddress((void**)&kh, g_kh);
    cudaGetSymbolAddress((void**)&v, g_v);
    cudaGetSymbolAddress((void**)&e, g_e);
    cudaGetSymbolAddress((void**)&rs, g_rs);

    cudaFuncSetAttribute(proj_kernel,  cudaFuncAttributeMaxDynamicSharedMemorySize, PSM);
    cudaFuncSetAttribute(score_kernel, cudaFuncAttributeMaxDynamicSharedMemorySize, PSM);
    cudaFuncSetAttribute(pv_kernel,    cudaFuncAttributeMaxDynamicSharedMemorySize, PVSM);

    const float scale = 1.0f / 32.0f;   // C^-0.5

    // 1) input conversions (x conv also zeroes rs)
    conv_h<<<(MT * CC + 255) / 256, 256>>>(x, xh, rs, MT * CC);
    conv3<<<dim3((CC * CC + 255) / 256, 3), 256>>>(Wq, Wk, Wv, wq, wk, wv, CC * CC);

    // 2) fused QKV projection, single-pass fp16
    proj_kernel<<<dim3(CC / 128, MT / 128, 3), 256, PSM>>>(
        xh, wq, wk, wv, qh, kh, v);

    // 3) e = exp(scale*q@k^T - 4), masked, fp16; row sums via atomics
    score_kernel<<<dim3(136, 1, BB), 256, PSM>>>(qh, kh, e, rs, scale);

    // 4) out = (E @ V) / rowsum
    pv_kernel<<<dim3(CC / 128, TT / 128, BB), 256, PVSM>>>(e, v, rs, out);
}